// round 2
// baseline (speedup 1.0000x reference)
#include <cuda_runtime.h>
#include <cstdint>

#define D     128
#define T     256          // axial line length (H == W == 256)
#define TILE  64           // positions per block
#define DPAD  132          // padded row (floats) for 128-wide tiles
#define MPAD  130          // padded row (floats) for transposed M
#define SCALE 0.08838834764831845f   // 128^-0.5

typedef unsigned long long ull;

// Per-axis precomputed M^T:  g_MT[c*128 + k] = (Wq^T Wk)[k,c] * SCALE
__device__ float g_MT_h[D * D];
__device__ float g_MT_w[D * D];

__device__ __forceinline__ ull ffma2(ull a, ull b, ull c) {
    ull d_;
    asm("fma.rn.f32x2 %0, %1, %2, %3;" : "=l"(d_) : "l"(a), "l"(b), "l"(c));
    return d_;
}

// ---------------------------------------------------------------------------
// Kernel 1: M^T[c][k] = sum_e Wq[e,k] * Wk[e,c] * SCALE   (per axis)
// grid (128, 2): blockIdx.x = k, blockIdx.y = axis (0 = width, 1 = height)
// ---------------------------------------------------------------------------
__global__ void compute_M_kernel(const float* __restrict__ Wq_h,
                                 const float* __restrict__ Wk_h,
                                 const float* __restrict__ Wq_w,
                                 const float* __restrict__ Wk_w) {
    int k    = blockIdx.x;     // K index of GEMM (row of M)
    int c    = threadIdx.x;    // output channel (col of M)
    int axis = blockIdx.y;
    const float* Wq = axis ? Wq_h : Wq_w;
    const float* Wk = axis ? Wk_h : Wk_w;
    float*       MT = axis ? g_MT_h : g_MT_w;

    __shared__ float sq[D];
    sq[c] = Wq[c * D + k];     // Wq column k (c plays 'e' here)
    __syncthreads();

    float s = 0.f;
#pragma unroll 8
    for (int e = 0; e < D; e++) s = fmaf(sq[e], Wk[e * D + c], s);
    MT[c * D + k] = s * SCALE;
}

// ---------------------------------------------------------------------------
// Kernel 2: fused  t = x@M  ->  banded dots -> band softmax -> attn @ kv
// One block = 64 consecutive positions of one axial line.
// AXIS_H = 0: width axis (contiguous lines), writes out.
// AXIS_H = 1: height axis (stride W*D), accumulates into out.
// ---------------------------------------------------------------------------
template <int AXIS_H>
__global__ __launch_bounds__(256, 1)
void axial_kernel(const float* __restrict__ x,
                  const float* __restrict__ kv,
                  float* __restrict__ out) {
    extern __shared__ float smem[];
    float* sm_M  = smem;                         // 128*130
    float* sm_X  = sm_M  + D * MPAD;             // 64*132 (aliased as O later)
    float* sm_T  = sm_X  + TILE * DPAD;          // 64*132
    float* sm_KV = sm_T  + TILE * DPAD;          // 66*132
    float* sm_dt = sm_KV + (TILE + 2) * DPAD;    // 64*4
    float* sm_O  = sm_X;                         // alias: X dead after GEMM

    const int tid  = threadIdx.x;
    const int line = blockIdx.x >> 2;
    const int tile = blockIdx.x & 3;
    const int p0   = tile * TILE;

    int base, sp;
    if (AXIS_H) {
        int b = line >> 8, w = line & 255;
        base = b * (T * T * D) + w * D;          // x[b, p, w, :]
        sp   = T * D;
    } else {
        base = line * (T * D);                   // x[b, h, p, :]
        sp   = D;
    }

    // ---- stage M^T into smem (L2-hot, 64KB) ----
    {
        const float2* src = (const float2*)(AXIS_H ? g_MT_h : g_MT_w);
        for (int i2 = tid; i2 < D * (D / 2); i2 += 256) {
            int c = i2 >> 6, k2 = i2 & 63;
            ((float2*)(sm_M + c * MPAD))[k2] = src[c * (D / 2) + k2];
        }
    }
    // ---- stage X tile ----
    for (int i4 = tid; i4 < TILE * (D / 4); i4 += 256) {
        int pos = i4 >> 5, c4 = i4 & 31;
        ((float4*)(sm_X + pos * DPAD))[c4] =
            ((const float4*)(x + base + (p0 + pos) * sp))[c4];
    }
    // ---- stage KV tile: positions p0-1 .. p0+64, zero-fill out of range ----
    for (int i4 = tid; i4 < (TILE + 2) * (D / 4); i4 += 256) {
        int j = i4 >> 5, c4 = i4 & 31;
        int gp = p0 - 1 + j;
        float4 v = make_float4(0.f, 0.f, 0.f, 0.f);
        if (gp >= 0 && gp < T)
            v = ((const float4*)(kv + base + gp * sp))[c4];
        ((float4*)(sm_KV + j * DPAD))[c4] = v;
    }
    __syncthreads();

    // ---- GEMM: T[pos, c] = sum_k X[pos,k] * M[k,c]  via fma.rn.f32x2 ----
    // k paired into f32x2 lanes (lo = even k, hi = odd k), summed at epilogue.
    {
        const int tx = tid & 15;      // cols c = tx + 16*j, j = 0..7
        const int ty = tid >> 4;      // rows r = 4*ty .. 4*ty+3
        ull acc[4][8];
#pragma unroll
        for (int i = 0; i < 4; i++)
#pragma unroll
            for (int j = 0; j < 8; j++) acc[i][j] = 0ull;

        const ull* Xr[4];
#pragma unroll
        for (int i = 0; i < 4; i++)
            Xr[i] = (const ull*)(sm_X + (ty * 4 + i) * DPAD);
        const ull* Bc[8];
#pragma unroll
        for (int j = 0; j < 8; j++)
            Bc[j] = (const ull*)(sm_M + (tx + 16 * j) * MPAD);

#pragma unroll 4
        for (int kp = 0; kp < D / 2; kp++) {
            ull a0 = Xr[0][kp], a1 = Xr[1][kp], a2 = Xr[2][kp], a3 = Xr[3][kp];
#pragma unroll
            for (int j = 0; j < 8; j++) {
                ull b = Bc[j][kp];
                acc[0][j] = ffma2(a0, b, acc[0][j]);
                acc[1][j] = ffma2(a1, b, acc[1][j]);
                acc[2][j] = ffma2(a2, b, acc[2][j]);
                acc[3][j] = ffma2(a3, b, acc[3][j]);
            }
        }
#pragma unroll
        for (int i = 0; i < 4; i++)
#pragma unroll
            for (int j = 0; j < 8; j++) {
                unsigned lo = (unsigned)acc[i][j];
                unsigned hi = (unsigned)(acc[i][j] >> 32);
                sm_T[(ty * 4 + i) * DPAD + tx + 16 * j] =
                    __uint_as_float(lo) + __uint_as_float(hi);
            }
    }
    __syncthreads();

    // ---- banded dots: dt[pos][dd] = t[pos] . kv[pos-1+dd], dd in {0,1,2} ----
    if (tid < 192) {
        int pos = tid & 63, dd = tid >> 6;
        const float4* tp = (const float4*)(sm_T + pos * DPAD);
        const float4* kp = (const float4*)(sm_KV + (pos + dd) * DPAD);
        float s = 0.f;
#pragma unroll 8
        for (int c4 = 0; c4 < 32; c4++) {
            float4 a = tp[c4], b = kp[c4];
            s += a.x * b.x + a.y * b.y + a.z * b.z + a.w * b.w;
        }
        sm_dt[pos * 4 + dd] = s;
    }
    __syncthreads();

    // ---- exact band softmax + weighted kv sum -> O (aliases X) ----
    {
        int pos = tid & 63, q = tid >> 6;     // q: which 32-channel slice
        int gp = p0 + pos;
        float d0 = sm_dt[pos * 4 + 0];
        float d1 = sm_dt[pos * 4 + 1];
        float d2 = sm_dt[pos * 4 + 2];
        float m = d1;
        if (gp > 0)     m = fmaxf(m, d0);
        if (gp < T - 1) m = fmaxf(m, d2);
        float w0 = (gp > 0)     ? __expf(d0 - m) : 0.f;
        float w1 = __expf(d1 - m);
        float w2 = (gp < T - 1) ? __expf(d2 - m) : 0.f;
        float inv = 1.f / (w0 + w1 + w2);
        float a0 = w0 * inv, a1 = w1 * inv, a2 = w2 * inv;

        const float4* k0 = (const float4*)(sm_KV + pos * DPAD);
        const float4* k1 = (const float4*)(sm_KV + (pos + 1) * DPAD);
        const float4* k2 = (const float4*)(sm_KV + (pos + 2) * DPAD);
        float4* op = (float4*)(sm_O + pos * DPAD);
#pragma unroll
        for (int u = 0; u < 8; u++) {
            int c4 = q * 8 + u;
            float4 v0 = k0[c4], v1 = k1[c4], v2 = k2[c4];
            float4 r;
            r.x = a0 * v0.x + a1 * v1.x + a2 * v2.x;
            r.y = a0 * v0.y + a1 * v1.y + a2 * v2.y;
            r.z = a0 * v0.z + a1 * v1.z + a2 * v2.z;
            r.w = a0 * v0.w + a1 * v1.w + a2 * v2.w;
            op[c4] = r;
        }
    }
    __syncthreads();

    // ---- coalesced writeback (height axis accumulates) ----
    for (int i4 = tid; i4 < TILE * (D / 4); i4 += 256) {
        int pos = i4 >> 5, c4 = i4 & 31;
        float4 v = ((const float4*)(sm_O + pos * DPAD))[c4];
        float4* go = (float4*)(out + base + (p0 + pos) * sp);
        if (AXIS_H) {
            float4 o = go[c4];
            v.x += o.x; v.y += o.y; v.z += o.z; v.w += o.w;
        }
        go[c4] = v;
    }
}

// ---------------------------------------------------------------------------
extern "C" void kernel_launch(void* const* d_in, const int* in_sizes, int n_in,
                              void* d_out, int out_size) {
    const float* x    = (const float*)d_in[0];
    const float* kv   = (const float*)d_in[1];
    const float* Wq_h = (const float*)d_in[2];
    const float* Wk_h = (const float*)d_in[3];
    const float* Wq_w = (const float*)d_in[4];
    const float* Wk_w = (const float*)d_in[5];
    float* out = (float*)d_out;

    constexpr int SMEM_FLOATS =
        D * MPAD + TILE * DPAD + TILE * DPAD + (TILE + 2) * DPAD + TILE * 4;
    constexpr int SMEM_BYTES = SMEM_FLOATS * 4;   // 170016 B

    // Idempotent; harness's correctness call happens before graph capture.
    cudaFuncSetAttribute(axial_kernel<0>,
                         cudaFuncAttributeMaxDynamicSharedMemorySize, SMEM_BYTES);
    cudaFuncSetAttribute(axial_kernel<1>,
                         cudaFuncAttributeMaxDynamicSharedMemorySize, SMEM_BYTES);

    compute_M_kernel<<<dim3(128, 2), 128>>>(Wq_h, Wk_h, Wq_w, Wk_w);

    const int nblocks = (4 * T) * (T / TILE);    // 1024 lines * 4 tiles = 4096
    axial_kernel<0><<<nblocks, 256, SMEM_BYTES>>>(x, kv, out);  // width: writes
    axial_kernel<1><<<nblocks, 256, SMEM_BYTES>>>(x, kv, out);  // height: accum
}

// round 3
// speedup vs baseline: 1.5448x; 1.5448x over previous
#include <cuda_runtime.h>
#include <cstdint>

#define D     128
#define T     256
#define TILE  128            // positions per tile
#define MPAD  130            // padded M row (floats)
#define SCALE 0.08838834764831845f   // 128^-0.5
#define NTILES 2048          // per axis: 1024 lines * 2 tiles

typedef unsigned long long ull;

// Per-axis precomputed M^T:  g_MT[c*128 + k] = (Wq^T Wk)[k,c] * SCALE
__device__ float g_MT_h[D * D];
__device__ float g_MT_w[D * D];

__device__ __forceinline__ ull ffma2(ull a, ull b, ull c) {
    ull d_;
    asm("fma.rn.f32x2 %0, %1, %2, %3;" : "=l"(d_) : "l"(a), "l"(b), "l"(c));
    return d_;
}

__device__ __forceinline__ uint32_t smem_u32(const void* p) {
    uint32_t a;
    asm("{ .reg .u64 t; cvta.to.shared.u64 t, %1; cvt.u32.u64 %0, t; }"
        : "=r"(a) : "l"(p));
    return a;
}

__device__ __forceinline__ void cpa16(uint32_t dst, const void* src, int srcsz) {
    asm volatile("cp.async.cg.shared.global [%0], [%1], 16, %2;"
                 :: "r"(dst), "l"(src), "r"(srcsz));
}
__device__ __forceinline__ void cpa_commit() {
    asm volatile("cp.async.commit_group;");
}
__device__ __forceinline__ void cpa_wait1() {
    asm volatile("cp.async.wait_group 1;");
}

// ---------------------------------------------------------------------------
// Kernel 1: M^T[c][k] = sum_e Wq[e,k] * Wk[e,c] * SCALE  (per axis)
// ---------------------------------------------------------------------------
__global__ void compute_M_kernel(const float* __restrict__ Wq_h,
                                 const float* __restrict__ Wk_h,
                                 const float* __restrict__ Wq_w,
                                 const float* __restrict__ Wk_w) {
    int k = blockIdx.x, c = threadIdx.x, axis = blockIdx.y;
    const float* Wq = axis ? Wq_h : Wq_w;
    const float* Wk = axis ? Wk_h : Wk_w;
    float*       MT = axis ? g_MT_h : g_MT_w;
    __shared__ float sq[D];
    sq[c] = Wq[c * D + k];
    __syncthreads();
    float s = 0.f;
#pragma unroll 8
    for (int e = 0; e < D; e++) s = fmaf(sq[e], Wk[e * D + c], s);
    MT[c * D + k] = s * SCALE;
}

// ---------------------------------------------------------------------------
// Kernel 2: persistent fused axial attention (one axis per launch).
// smem: M^T 128x130 | X 128x128 | KV 130x128 | partials 3*128*17 | dt 128*4
// ---------------------------------------------------------------------------
#define SMEM_FLOATS (D * MPAD + TILE * D + (TILE + 2) * D + 3 * TILE * 17 + TILE * 4)

template <int AXIS_H>
__global__ __launch_bounds__(256, 1)
void axial_persist(const float* __restrict__ x,
                   const float* __restrict__ kv,
                   float* __restrict__ out) {
    extern __shared__ float smem[];
    float* sm_M  = smem;                        // 128*130
    float* sm_X  = sm_M  + D * MPAD;            // 128*128
    float* sm_KV = sm_X  + TILE * D;            // 130*128
    float* sm_pt = sm_KV + (TILE + 2) * D;      // 3*128*17
    float* sm_dt = sm_pt + 3 * TILE * 17;       // 128*4

    const int tid = threadIdx.x;
    const uint32_t uX  = smem_u32(sm_X);
    const uint32_t uKV = smem_u32(sm_KV);

    // ---- stage M^T once per CTA (padded rows) ----
    {
        const float2* src = (const float2*)(AXIS_H ? g_MT_h : g_MT_w);
        for (int i2 = tid; i2 < D * (D / 2); i2 += 256) {
            int c = i2 >> 6, k2 = i2 & 63;
            ((float2*)(sm_M + c * MPAD))[k2] = src[c * (D / 2) + k2];
        }
    }

    // tile -> addressing helpers
    auto tile_base = [](int t, int& base, int& sp, int& p0) {
        int line = t >> 1;
        p0 = (t & 1) * TILE;
        if (AXIS_H) {
            int b = line >> 8, w = line & 255;
            base = b * (T * T * D) + w * D;
            sp   = T * D;
        } else {
            base = line * (T * D);
            sp   = D;
        }
    };

    auto stage_X = [&](int t) {
        int base, sp, p0; tile_base(t, base, sp, p0);
        for (int ch = tid; ch < TILE * 32; ch += 256) {
            int pos = ch >> 5, c = ch & 31;
            cpa16(uX + (uint32_t)(pos * D + c * 4) * 4,
                  x + base + (p0 + pos) * sp + c * 4, 16);
        }
    };
    auto stage_KV = [&](int t) {
        int base, sp, p0; tile_base(t, base, sp, p0);
        for (int ch = tid; ch < (TILE + 2) * 32; ch += 256) {
            int row = ch >> 5, c = ch & 31;
            int gp = p0 - 1 + row;
            bool ok = (gp >= 0) && (gp < T);
            const float* src = kv + base + (ok ? gp * sp : 0) + c * 4;
            cpa16(uKV + (uint32_t)(row * D + c * 4) * 4, src, ok ? 16 : 0);
        }
    };

    const int tx = tid & 15;     // cols c = tx + 16*j
    const int ty = tid >> 4;     // rows r = ty + 16*i

    int t = blockIdx.x;
    if (t < NTILES) { stage_X(t); }
    cpa_commit();
    if (t < NTILES) { stage_KV(t); }
    cpa_commit();

    for (; t < NTILES; t += gridDim.x) {
        const int tn = t + gridDim.x;
        int base, sp, p0; tile_base(t, base, sp, p0);

        cpa_wait1();          // X(t) ready (KV(t) may still be in flight)
        __syncthreads();

        // ---- GEMM: t[r,c] = sum_k X[r,k] M[k,c], 8x8 per thread, f32x2 on k ----
        ull acc[8][8];
#pragma unroll
        for (int i = 0; i < 8; i++)
#pragma unroll
            for (int j = 0; j < 8; j++) acc[i][j] = 0ull;

        {
            const ull* Xr[8];
            const ull* Bc[8];
#pragma unroll
            for (int i = 0; i < 8; i++)
                Xr[i] = (const ull*)(sm_X + (ty + 16 * i) * D);
#pragma unroll
            for (int j = 0; j < 8; j++)
                Bc[j] = (const ull*)(sm_M + (tx + 16 * j) * MPAD);

#pragma unroll 4
            for (int kp = 0; kp < D / 2; kp++) {
                ull a0 = Xr[0][kp], a1 = Xr[1][kp], a2 = Xr[2][kp], a3 = Xr[3][kp];
                ull a4 = Xr[4][kp], a5 = Xr[5][kp], a6 = Xr[6][kp], a7 = Xr[7][kp];
#pragma unroll
                for (int j = 0; j < 8; j++) {
                    ull b = Bc[j][kp];
                    acc[0][j] = ffma2(a0, b, acc[0][j]);
                    acc[1][j] = ffma2(a1, b, acc[1][j]);
                    acc[2][j] = ffma2(a2, b, acc[2][j]);
                    acc[3][j] = ffma2(a3, b, acc[3][j]);
                    acc[4][j] = ffma2(a4, b, acc[4][j]);
                    acc[5][j] = ffma2(a5, b, acc[5][j]);
                    acc[6][j] = ffma2(a6, b, acc[6][j]);
                    acc[7][j] = ffma2(a7, b, acc[7][j]);
                }
            }
        }
        __syncthreads();      // everyone done reading sm_X

        // prefetch next tile's X into the freed buffer (overlaps epilogue)
        if (tn < NTILES) stage_X(tn);
        cpa_commit();

        cpa_wait1();          // KV(t) ready (pending: X(tn))
        __syncthreads();

        // ---- fold f32x2 lanes, banded partial dots vs KV ----
        {
            float tv[8][8];
#pragma unroll
            for (int i = 0; i < 8; i++)
#pragma unroll
                for (int j = 0; j < 8; j++) {
                    unsigned lo = (unsigned)acc[i][j];
                    unsigned hi = (unsigned)(acc[i][j] >> 32);
                    tv[i][j] = __uint_as_float(lo) + __uint_as_float(hi);
                }
#pragma unroll
            for (int i = 0; i < 8; i++) {
                int r = ty + 16 * i;
                float p0d = 0.f, p1d = 0.f, p2d = 0.f;
#pragma unroll
                for (int j = 0; j < 8; j++) {
                    int c = tx + 16 * j;
                    p0d = fmaf(tv[i][j], sm_KV[(r + 0) * D + c], p0d);
                    p1d = fmaf(tv[i][j], sm_KV[(r + 1) * D + c], p1d);
                    p2d = fmaf(tv[i][j], sm_KV[(r + 2) * D + c], p2d);
                }
                sm_pt[(0 * TILE + r) * 17 + tx] = p0d;
                sm_pt[(1 * TILE + r) * 17 + tx] = p1d;
                sm_pt[(2 * TILE + r) * 17 + tx] = p2d;
            }
        }
        __syncthreads();

        // ---- reduce partials -> raw dots ----
        for (int s = tid; s < 3 * TILE; s += 256) {
            int pos = s & (TILE - 1), dd = s >> 7;
            const float* pp = sm_pt + (dd * TILE + pos) * 17;
            float sum = 0.f;
#pragma unroll
            for (int u = 0; u < 16; u++) sum += pp[u];
            sm_dt[pos * 4 + dd] = sum;
        }
        __syncthreads();

        // ---- exact band softmax ----
        if (tid < TILE) {
            int pos = tid, gp = p0 + pos;
            float d0 = sm_dt[pos * 4 + 0];
            float d1 = sm_dt[pos * 4 + 1];
            float d2 = sm_dt[pos * 4 + 2];
            float m = d1;
            if (gp > 0)     m = fmaxf(m, d0);
            if (gp < T - 1) m = fmaxf(m, d2);
            float w0 = (gp > 0)     ? __expf(d0 - m) : 0.f;
            float w1 = __expf(d1 - m);
            float w2 = (gp < T - 1) ? __expf(d2 - m) : 0.f;
            float inv = 1.f / (w0 + w1 + w2);
            sm_dt[pos * 4 + 0] = w0 * inv;
            sm_dt[pos * 4 + 1] = w1 * inv;
            sm_dt[pos * 4 + 2] = w2 * inv;
        }
        __syncthreads();

        // ---- weighted kv sum -> global out (AXIS_H accumulates) ----
        {
            int pos = tid >> 1, half = tid & 1;
            float a0 = sm_dt[pos * 4 + 0];
            float a1 = sm_dt[pos * 4 + 1];
            float a2 = sm_dt[pos * 4 + 2];
            const float4* k0 = (const float4*)(sm_KV + (pos + 0) * D);
            const float4* k1 = (const float4*)(sm_KV + (pos + 1) * D);
            const float4* k2 = (const float4*)(sm_KV + (pos + 2) * D);
            float4* go = (float4*)(out + base + (p0 + pos) * sp);
#pragma unroll
            for (int u = 0; u < 16; u++) {
                int c4 = half * 16 + u;
                float4 v0 = k0[c4], v1 = k1[c4], v2 = k2[c4];
                float4 r;
                r.x = a0 * v0.x + a1 * v1.x + a2 * v2.x;
                r.y = a0 * v0.y + a1 * v1.y + a2 * v2.y;
                r.z = a0 * v0.z + a1 * v1.z + a2 * v2.z;
                r.w = a0 * v0.w + a1 * v1.w + a2 * v2.w;
                if (AXIS_H) {
                    float4 o = go[c4];
                    r.x += o.x; r.y += o.y; r.z += o.z; r.w += o.w;
                }
                go[c4] = r;
            }
        }
        __syncthreads();      // everyone done reading sm_KV / sm_dt

        if (tn < NTILES) stage_KV(tn);
        cpa_commit();
    }
}

// ---------------------------------------------------------------------------
extern "C" void kernel_launch(void* const* d_in, const int* in_sizes, int n_in,
                              void* d_out, int out_size) {
    const float* x    = (const float*)d_in[0];
    const float* kv   = (const float*)d_in[1];
    const float* Wq_h = (const float*)d_in[2];
    const float* Wk_h = (const float*)d_in[3];
    const float* Wq_w = (const float*)d_in[4];
    const float* Wk_w = (const float*)d_in[5];
    float* out = (float*)d_out;

    constexpr int SMEM_BYTES = SMEM_FLOATS * 4;   // 226816 B

    cudaFuncSetAttribute(axial_persist<0>,
                         cudaFuncAttributeMaxDynamicSharedMemorySize, SMEM_BYTES);
    cudaFuncSetAttribute(axial_persist<1>,
                         cudaFuncAttributeMaxDynamicSharedMemorySize, SMEM_BYTES);

    int nsm = 148;
    cudaDeviceGetAttribute(&nsm, cudaDevAttrMultiProcessorCount, 0);
    if (nsm <= 0) nsm = 148;
    if (nsm > NTILES) nsm = NTILES;

    compute_M_kernel<<<dim3(128, 2), 128>>>(Wq_h, Wk_h, Wq_w, Wk_w);
    axial_persist<0><<<nsm, 256, SMEM_BYTES>>>(x, kv, out);  // width: writes
    axial_persist<1><<<nsm, 256, SMEM_BYTES>>>(x, kv, out);  // height: accum
}

// round 5
// speedup vs baseline: 2.1765x; 1.4089x over previous
#include <cuda_runtime.h>
#include <cuda_bf16.h>
#include <cstdint>

#define D 128
#define T 256
#define NTILES 2048          // per axis: 1024 lines * 2 tiles of 128
#define SCALE 0.08838834764831845f   // 128^-0.5
#define KF_PITCH 132         // fp32 KV row pitch (528B)
#define PITCH 136            // bf16 row pitch for X/M tiles (272B rows)

typedef unsigned long long ull;

// Per-axis precomputed M^T (fp32): g_MT[c*128 + k] = (Wq^T Wk)[k,c] * SCALE
__device__ float g_MT_h[D * D];
__device__ float g_MT_w[D * D];

// ---- smem byte layout ----
#define OFF_MH 0                          // bf16 M hi [128c][PITCH]
#define OFF_ML (OFF_MH + 34816)           // bf16 M lo
#define OFF_XH (OFF_ML + 34816)           // bf16 X hi [128r][PITCH]
#define OFF_XL (OFF_XH + 34816)           // bf16 X lo
#define OFF_XF (OFF_XL + 34816)           // fp32 X staging: 2 x 8KB chunk slots
#define OFF_KF (OFF_XF + 16384)           // fp32 KV: 130 x 132
#define SMEM_TOTAL (OFF_KF + 130 * KF_PITCH * 4)   // 224288 B
// overlays on XF (dead between convert(t) and stage(t+1)):
#define OFF_PT OFF_XF                     // partials [3][128][2] fp32 = 3072B
#define OFF_DT (OFF_XF + 3072)            // weights  [128][4] fp32   = 2048B

// ---------------------------------------------------------------------------
__device__ __forceinline__ uint32_t smem_u32(const void* p) {
    uint32_t a;
    asm("{ .reg .u64 t; cvta.to.shared.u64 t, %1; cvt.u32.u64 %0, t; }"
        : "=r"(a) : "l"(p));
    return a;
}
__device__ __forceinline__ void cpa16(uint32_t dst, const void* src, int srcsz) {
    asm volatile("cp.async.cg.shared.global [%0], [%1], 16, %2;"
                 :: "r"(dst), "l"(src), "r"(srcsz));
}
__device__ __forceinline__ void cpa_commit() {
    asm volatile("cp.async.commit_group;");
}
__device__ __forceinline__ void cpa_wait0() {
    asm volatile("cp.async.wait_group 0;" ::: "memory");
}
__device__ __forceinline__ void cpa_wait1() {
    asm volatile("cp.async.wait_group 1;" ::: "memory");
}
__device__ __forceinline__ void ldsm4(uint32_t* r, uint32_t a) {
    asm volatile("ldmatrix.sync.aligned.m8n8.x4.shared.b16 {%0,%1,%2,%3}, [%4];"
                 : "=r"(r[0]), "=r"(r[1]), "=r"(r[2]), "=r"(r[3]) : "r"(a));
}
__device__ __forceinline__ void mmabf(float* d, const uint32_t* a,
                                      uint32_t b0, uint32_t b1) {
    asm volatile(
        "mma.sync.aligned.m16n8k16.row.col.f32.bf16.bf16.f32 "
        "{%0,%1,%2,%3},{%4,%5,%6,%7},{%8,%9},{%0,%1,%2,%3};"
        : "+f"(d[0]), "+f"(d[1]), "+f"(d[2]), "+f"(d[3])
        : "r"(a[0]), "r"(a[1]), "r"(a[2]), "r"(a[3]), "r"(b0), "r"(b1));
}

// fp32 -> (bf16 hi, bf16 lo) split, 4 elems -> two 8B words
__device__ __forceinline__ void split4(float4 v, ull& hw, ull& lw) {
    __nv_bfloat162 h0 = __floats2bfloat162_rn(v.x, v.y);
    __nv_bfloat162 h1 = __floats2bfloat162_rn(v.z, v.w);
    float2 f0 = __bfloat1622float2(h0);
    float2 f1 = __bfloat1622float2(h1);
    __nv_bfloat162 l0 = __floats2bfloat162_rn(v.x - f0.x, v.y - f0.y);
    __nv_bfloat162 l1 = __floats2bfloat162_rn(v.z - f1.x, v.w - f1.y);
    unsigned uh0 = *(unsigned*)&h0, uh1 = *(unsigned*)&h1;
    unsigned ul0 = *(unsigned*)&l0, ul1 = *(unsigned*)&l1;
    hw = (ull)uh0 | ((ull)uh1 << 32);
    lw = (ull)ul0 | ((ull)ul1 << 32);
}

// ---------------------------------------------------------------------------
// Kernel 1: M^T[c][k] = sum_e Wq[e,k] * Wk[e,c] * SCALE  (per axis)
// ---------------------------------------------------------------------------
__global__ void compute_M_kernel(const float* __restrict__ Wq_h,
                                 const float* __restrict__ Wk_h,
                                 const float* __restrict__ Wq_w,
                                 const float* __restrict__ Wk_w) {
    int k = blockIdx.x, c = threadIdx.x, axis = blockIdx.y;
    const float* Wq = axis ? Wq_h : Wq_w;
    const float* Wk = axis ? Wk_h : Wk_w;
    float*       MT = axis ? g_MT_h : g_MT_w;
    __shared__ float sq[D];
    sq[c] = Wq[c * D + k];
    __syncthreads();
    float s = 0.f;
#pragma unroll 8
    for (int e = 0; e < D; e++) s = fmaf(sq[e], Wk[e * D + c], s);
    MT[c * D + k] = s * SCALE;
}

// ---------------------------------------------------------------------------
// Kernel 2: persistent HMMA fused axial attention (one axis per launch)
// ---------------------------------------------------------------------------
template <int AXIS_H>
__global__ __launch_bounds__(256, 1)
void axial_mma(const float* __restrict__ x, const float* __restrict__ kv,
               float* __restrict__ out) {
    extern __shared__ char sm[];
    const uint32_t sb = smem_u32(sm);
    const int tid = threadIdx.x, wid = tid >> 5, lane = tid & 31;
    const int rg = wid >> 1, cg = wid & 1;       // row-group, col-group
    const int qrow = lane >> 2, qc = lane & 3;

    // ---- stage + split M^T once per CTA ----
    {
        const float4* MT4 = (const float4*)(AXIS_H ? g_MT_h : g_MT_w);
        for (int s = tid; s < D * 32; s += 256) {
            int r = s >> 5, c8 = (s & 31) * 8;
            float4 v = MT4[s];
            ull hw, lw; split4(v, hw, lw);
            *(ull*)(sm + OFF_MH + r * 272 + c8) = hw;
            *(ull*)(sm + OFF_ML + r * 272 + c8) = lw;
        }
    }

    auto tile_base = [](int t, int& base, int& sp, int& p0) {
        int line = t >> 1;
        p0 = (t & 1) * 128;
        if (AXIS_H) {
            int b = line >> 8, w = line & 255;
            base = b * (T * T * D) + w * D;
            sp   = T * D;
        } else {
            base = line * (T * D);
            sp   = D;
        }
    };

    auto stage_x_chunk = [&](int t, int q) {   // 16 rows -> XF slot (q&1)
        int base, sp, p0; tile_base(t, base, sp, p0);
        uint32_t dst = sb + OFF_XF + (uint32_t)(q & 1) * 8192;
#pragma unroll
        for (int u = 0; u < 2; u++) {
            int s = tid + u * 256;
            int rl = s >> 5, c4 = s & 31;
            cpa16(dst + (uint32_t)s * 16,
                  x + base + (p0 + q * 16 + rl) * sp + c4 * 4, 16);
        }
    };
    auto convert_chunk = [&](int q) {          // XF slot -> XH/XL bf16 split
        const char* src = sm + OFF_XF + (q & 1) * 8192;
#pragma unroll
        for (int u = 0; u < 2; u++) {
            int s = tid + u * 256;
            int rl = s >> 5, c4 = s & 31;
            float4 v = *(const float4*)(src + s * 16);
            ull hw, lw; split4(v, hw, lw);
            uint32_t off = (uint32_t)(q * 16 + rl) * 272 + (uint32_t)c4 * 8;
            *(ull*)(sm + OFF_XH + off) = hw;
            *(ull*)(sm + OFF_XL + off) = lw;
        }
    };
    auto xpipe = [&](int t) {                  // chunk0 must be committed
#pragma unroll 1
        for (int q = 0; q < 8; q++) {
            if (q < 7) { stage_x_chunk(t, q + 1); cpa_commit(); cpa_wait1(); }
            else       { cpa_wait0(); }
            convert_chunk(q);
            __syncthreads();                   // protect slot reuse
        }
    };
    auto stage_kv = [&](int t) {
        int base, sp, p0; tile_base(t, base, sp, p0);
        for (int s = tid; s < 130 * 32; s += 256) {
            int row = s >> 5, c4 = s & 31;
            int gp = p0 - 1 + row;
            bool ok = (gp >= 0) && (gp < T);
            cpa16(sb + OFF_KF + (uint32_t)(row * KF_PITCH + c4 * 4) * 4,
                  kv + base + (ok ? gp * sp : 0) + c4 * 4, ok ? 16 : 0);
        }
    };

    // per-thread ldmatrix base offsets
    uint32_t aoffH[2], aoffL[2], boffH[4], boffL[4];
#pragma unroll
    for (int mi = 0; mi < 2; mi++) {
        uint32_t b = (uint32_t)(32 * rg + 16 * mi + (lane & 15)) * 272
                   + ((uint32_t)(lane >> 4) << 4);
        aoffH[mi] = sb + OFF_XH + b;
        aoffL[mi] = sb + OFF_XL + b;
    }
#pragma unroll
    for (int ng = 0; ng < 4; ng++) {
        uint32_t b = (uint32_t)(64 * cg + 16 * ng + ((lane >> 4) << 3) + (lane & 7)) * 272
                   + (((uint32_t)(lane >> 3) & 1) << 4);
        boffH[ng] = sb + OFF_MH + b;
        boffL[ng] = sb + OFF_ML + b;
    }

    const int t0 = blockIdx.x, stride = gridDim.x;

    // ---- prologue ----
    stage_x_chunk(t0, 0); cpa_commit();
    xpipe(t0);
    stage_kv(t0); cpa_commit();
    __syncthreads();

    for (int t = t0; t < NTILES; t += stride) {
        const int tn = t + stride;
        const bool hn = tn < NTILES;
        int base, sp, p0; tile_base(t, base, sp, p0);

        // ---- GEMM: acc = Xh@Mh + Xh@Ml + Xl@Mh ----
        float acc[2][8][4];
#pragma unroll
        for (int mi = 0; mi < 2; mi++)
#pragma unroll
            for (int nt = 0; nt < 8; nt++)
#pragma unroll
                for (int u = 0; u < 4; u++) acc[mi][nt][u] = 0.f;

#pragma unroll 1
        for (int ks = 0; ks < 8; ks++) {
            const uint32_t ko = (uint32_t)ks * 32;
            uint32_t ah[2][4], al[2][4], bh[4][4], bl[4][4];
#pragma unroll
            for (int mi = 0; mi < 2; mi++) {
                ldsm4(ah[mi], aoffH[mi] + ko);
                ldsm4(al[mi], aoffL[mi] + ko);
            }
#pragma unroll
            for (int ng = 0; ng < 4; ng++) {
                ldsm4(bh[ng], boffH[ng] + ko);
                ldsm4(bl[ng], boffL[ng] + ko);
            }
#pragma unroll
            for (int mi = 0; mi < 2; mi++)
#pragma unroll
                for (int ng = 0; ng < 4; ng++) {
                    mmabf(acc[mi][2 * ng],     ah[mi], bh[ng][0], bh[ng][1]);
                    mmabf(acc[mi][2 * ng + 1], ah[mi], bh[ng][2], bh[ng][3]);
                    mmabf(acc[mi][2 * ng],     ah[mi], bl[ng][0], bl[ng][1]);
                    mmabf(acc[mi][2 * ng + 1], ah[mi], bl[ng][2], bl[ng][3]);
                    mmabf(acc[mi][2 * ng],     al[mi], bh[ng][0], bh[ng][1]);
                    mmabf(acc[mi][2 * ng + 1], al[mi], bh[ng][2], bh[ng][3]);
                }
        }

        cpa_wait0();     // KV(t) landed (only pending group)

        // ---- banded dots from register accumulators ----
        {
            const float* KF = (const float*)(sm + OFF_KF);
            float prt[12];
#pragma unroll
            for (int mi = 0; mi < 2; mi++)
#pragma unroll
                for (int h = 0; h < 2; h++) {
                    int r = 32 * rg + 16 * mi + 8 * h + qrow;
#pragma unroll
                    for (int dd = 0; dd < 3; dd++) {
                        float s = 0.f;
#pragma unroll
                        for (int nt = 0; nt < 8; nt++) {
                            int c = 64 * cg + 8 * nt + 2 * qc;
                            float2 kp = *(const float2*)(KF + (r + dd) * KF_PITCH + c);
                            s = fmaf(acc[mi][nt][2 * h],     kp.x, s);
                            s = fmaf(acc[mi][nt][2 * h + 1], kp.y, s);
                        }
                        prt[(mi * 2 + h) * 3 + dd] = s;
                    }
                }
#pragma unroll
            for (int i = 0; i < 12; i++) {
                float v = prt[i];
                v += __shfl_xor_sync(0xffffffffu, v, 1);
                v += __shfl_xor_sync(0xffffffffu, v, 2);
                prt[i] = v;
            }
            if (qc == 0) {
                float* PT = (float*)(sm + OFF_PT);
#pragma unroll
                for (int mi = 0; mi < 2; mi++)
#pragma unroll
                    for (int h = 0; h < 2; h++) {
                        int r = 32 * rg + 16 * mi + 8 * h + qrow;
#pragma unroll
                        for (int dd = 0; dd < 3; dd++)
                            PT[(dd * 128 + r) * 2 + cg] = prt[(mi * 2 + h) * 3 + dd];
                    }
            }
        }
        __syncthreads();

        // ---- exact band softmax ----
        if (tid < 128) {
            const float* PT = (const float*)(sm + OFF_PT);
            float* DT = (float*)(sm + OFF_DT);
            int pos = tid, gp = p0 + pos;
            float d0 = PT[(0 * 128 + pos) * 2] + PT[(0 * 128 + pos) * 2 + 1];
            float d1 = PT[(1 * 128 + pos) * 2] + PT[(1 * 128 + pos) * 2 + 1];
            float d2 = PT[(2 * 128 + pos) * 2] + PT[(2 * 128 + pos) * 2 + 1];
            float m = d1;
            if (gp > 0)     m = fmaxf(m, d0);
            if (gp < T - 1) m = fmaxf(m, d2);
            float w0 = (gp > 0)     ? __expf(d0 - m) : 0.f;
            float w1 = __expf(d1 - m);
            float w2 = (gp < T - 1) ? __expf(d2 - m) : 0.f;
            float inv = 1.f / (w0 + w1 + w2);
            DT[pos * 4 + 0] = w0 * inv;
            DT[pos * 4 + 1] = w1 * inv;
            DT[pos * 4 + 2] = w2 * inv;
        }
        __syncthreads();

        // ---- weighted kv sum -> global out (AXIS_H accumulates) ----
        {
            const float* DT = (const float*)(sm + OFF_DT);
            const float4* kf4 = (const float4*)(sm + OFF_KF);
            int pos = tid >> 1, hf = tid & 1;
            float a0 = DT[pos * 4 + 0];
            float a1 = DT[pos * 4 + 1];
            float a2 = DT[pos * 4 + 2];
            const float4* k0 = kf4 + (pos + 0) * (KF_PITCH / 4);
            const float4* k1 = kf4 + (pos + 1) * (KF_PITCH / 4);
            const float4* k2 = kf4 + (pos + 2) * (KF_PITCH / 4);
            float4* go = (float4*)(out + base + (p0 + pos) * sp);
#pragma unroll
            for (int u = 0; u < 16; u++) {
                int c4 = hf * 16 + u;
                float4 v0 = k0[c4], v1 = k1[c4], v2 = k2[c4];
                float4 r;
                r.x = a0 * v0.x + a1 * v1.x + a2 * v2.x;
                r.y = a0 * v0.y + a1 * v1.y + a2 * v2.y;
                r.z = a0 * v0.z + a1 * v1.z + a2 * v2.z;
                r.w = a0 * v0.w + a1 * v1.w + a2 * v2.w;
                if (AXIS_H) {
                    float4 o = go[c4];
                    r.x += o.x; r.y += o.y; r.z += o.z; r.w += o.w;
                }
                go[c4] = r;
            }
        }
        __syncthreads();   // KF/DT reads done; XF overlay free

        if (hn) {
            stage_x_chunk(tn, 0); cpa_commit();
            xpipe(tn);                       // fills XH/XL(tn)
            stage_kv(tn); cpa_commit();      // overlaps next GEMM
        }
        __syncthreads();
    }
}

// ---------------------------------------------------------------------------
extern "C" void kernel_launch(void* const* d_in, const int* in_sizes, int n_in,
                              void* d_out, int out_size) {
    const float* x    = (const float*)d_in[0];
    const float* kv   = (const float*)d_in[1];
    const float* Wq_h = (const float*)d_in[2];
    const float* Wk_h = (const float*)d_in[3];
    const float* Wq_w = (const float*)d_in[4];
    const float* Wk_w = (const float*)d_in[5];
    float* out = (float*)d_out;

    cudaFuncSetAttribute(axial_mma<0>,
                         cudaFuncAttributeMaxDynamicSharedMemorySize, SMEM_TOTAL);
    cudaFuncSetAttribute(axial_mma<1>,
                         cudaFuncAttributeMaxDynamicSharedMemorySize, SMEM_TOTAL);

    int nsm = 148;
    cudaDeviceGetAttribute(&nsm, cudaDevAttrMultiProcessorCount, 0);
    if (nsm <= 0) nsm = 148;
    if (nsm > NTILES) nsm = NTILES;

    compute_M_kernel<<<dim3(128, 2), 128>>>(Wq_h, Wk_h, Wq_w, Wk_w);
    axial_mma<0><<<nsm, 256, SMEM_TOTAL>>>(x, kv, out);   // width: writes
    axial_mma<1><<<nsm, 256, SMEM_TOTAL>>>(x, kv, out);   // height: accumulates
}

// round 6
// speedup vs baseline: 2.1767x; 1.0001x over previous
#include <cuda_runtime.h>
#include <cuda_bf16.h>
#include <cstdint>

#define D 128
#define T 256
#define NTILES 2048          // per axis: 1024 lines * 2 tiles of 128
#define SCALE 0.08838834764831845f   // 128^-0.5
#define KF_PITCH 132         // fp32 KV row pitch (528B)
#define PITCH 136            // bf16 row pitch for X/M tiles (272B rows)

typedef unsigned long long ull;

// Per-axis precomputed M^T (fp32): g_MT[c*128 + k] = (Wq^T Wk)[k,c] * SCALE
__device__ float g_MT_h[D * D];
__device__ float g_MT_w[D * D];

// ---- smem byte layout ----
#define OFF_MH 0                          // bf16 M hi [128c][PITCH]
#define OFF_ML (OFF_MH + 34816)           // bf16 M lo
#define OFF_XH (OFF_ML + 34816)           // bf16 X hi [128r][PITCH]
#define OFF_XL (OFF_XH + 34816)           // bf16 X lo
#define OFF_XF (OFF_XL + 34816)           // fp32 X staging: 2 x 8KB chunk slots
#define OFF_KF (OFF_XF + 16384)           // fp32 KV: 130 x 132
#define SMEM_TOTAL (OFF_KF + 130 * KF_PITCH * 4)   // 224288 B
// overlays on XF (dead between convert(t) and stage(t+1)):
#define OFF_PT OFF_XF                     // partials [3][128][2] fp32 = 3072B
#define OFF_DT (OFF_XF + 3072)            // weights  [128][4] fp32   = 2048B

// ---------------------------------------------------------------------------
__device__ __forceinline__ uint32_t smem_u32(const void* p) {
    uint32_t a;
    asm("{ .reg .u64 t; cvta.to.shared.u64 t, %1; cvt.u32.u64 %0, t; }"
        : "=r"(a) : "l"(p));
    return a;
}
__device__ __forceinline__ void cpa16(uint32_t dst, const void* src, int srcsz) {
    asm volatile("cp.async.cg.shared.global [%0], [%1], 16, %2;"
                 :: "r"(dst), "l"(src), "r"(srcsz));
}
__device__ __forceinline__ void cpa_commit() {
    asm volatile("cp.async.commit_group;");
}
__device__ __forceinline__ void cpa_wait0() {
    asm volatile("cp.async.wait_group 0;" ::: "memory");
}
__device__ __forceinline__ void cpa_wait1() {
    asm volatile("cp.async.wait_group 1;" ::: "memory");
}
__device__ __forceinline__ void ldsm4(uint32_t* r, uint32_t a) {
    asm volatile("ldmatrix.sync.aligned.m8n8.x4.shared.b16 {%0,%1,%2,%3}, [%4];"
                 : "=r"(r[0]), "=r"(r[1]), "=r"(r[2]), "=r"(r[3]) : "r"(a));
}
__device__ __forceinline__ void mmabf(float* d, const uint32_t* a,
                                      uint32_t b0, uint32_t b1) {
    asm volatile(
        "mma.sync.aligned.m16n8k16.row.col.f32.bf16.bf16.f32 "
        "{%0,%1,%2,%3},{%4,%5,%6,%7},{%8,%9},{%0,%1,%2,%3};"
        : "+f"(d[0]), "+f"(d[1]), "+f"(d[2]), "+f"(d[3])
        : "r"(a[0]), "r"(a[1]), "r"(a[2]), "r"(a[3]), "r"(b0), "r"(b1));
}

// fp32 -> (bf16 hi, bf16 lo) split, 4 elems -> two 8B words
__device__ __forceinline__ void split4(float4 v, ull& hw, ull& lw) {
    __nv_bfloat162 h0 = __floats2bfloat162_rn(v.x, v.y);
    __nv_bfloat162 h1 = __floats2bfloat162_rn(v.z, v.w);
    float2 f0 = __bfloat1622float2(h0);
    float2 f1 = __bfloat1622float2(h1);
    __nv_bfloat162 l0 = __floats2bfloat162_rn(v.x - f0.x, v.y - f0.y);
    __nv_bfloat162 l1 = __floats2bfloat162_rn(v.z - f1.x, v.w - f1.y);
    unsigned uh0 = *(unsigned*)&h0, uh1 = *(unsigned*)&h1;
    unsigned ul0 = *(unsigned*)&l0, ul1 = *(unsigned*)&l1;
    hw = (ull)uh0 | ((ull)uh1 << 32);
    lw = (ull)ul0 | ((ull)ul1 << 32);
}

// ---------------------------------------------------------------------------
// Kernel 1: M^T[c][k] = sum_e Wq[e,k] * Wk[e,c] * SCALE  (per axis)
// ---------------------------------------------------------------------------
__global__ void compute_M_kernel(const float* __restrict__ Wq_h,
                                 const float* __restrict__ Wk_h,
                                 const float* __restrict__ Wq_w,
                                 const float* __restrict__ Wk_w) {
    int k = blockIdx.x, c = threadIdx.x, axis = blockIdx.y;
    const float* Wq = axis ? Wq_h : Wq_w;
    const float* Wk = axis ? Wk_h : Wk_w;
    float*       MT = axis ? g_MT_h : g_MT_w;
    __shared__ float sq[D];
    sq[c] = Wq[c * D + k];
    __syncthreads();
    float s = 0.f;
#pragma unroll 8
    for (int e = 0; e < D; e++) s = fmaf(sq[e], Wk[e * D + c], s);
    MT[c * D + k] = s * SCALE;
}

// ---------------------------------------------------------------------------
// Kernel 2: persistent HMMA fused axial attention (one axis per launch)
// ---------------------------------------------------------------------------
template <int AXIS_H>
__global__ __launch_bounds__(256, 1)
void axial_mma(const float* __restrict__ x, const float* __restrict__ kv,
               float* __restrict__ out) {
    extern __shared__ char sm[];
    const uint32_t sb = smem_u32(sm);
    const int tid = threadIdx.x, wid = tid >> 5, lane = tid & 31;
    const int rg = wid >> 1, cg = wid & 1;       // row-group, col-group
    const int qrow = lane >> 2, qc = lane & 3;

    // ---- stage + split M^T once per CTA ----
    {
        const float4* MT4 = (const float4*)(AXIS_H ? g_MT_h : g_MT_w);
        for (int s = tid; s < D * 32; s += 256) {
            int r = s >> 5, c8 = (s & 31) * 8;
            float4 v = MT4[s];
            ull hw, lw; split4(v, hw, lw);
            *(ull*)(sm + OFF_MH + r * 272 + c8) = hw;
            *(ull*)(sm + OFF_ML + r * 272 + c8) = lw;
        }
    }

    auto tile_base = [](int t, int& base, int& sp, int& p0) {
        int line = t >> 1;
        p0 = (t & 1) * 128;
        if (AXIS_H) {
            int b = line >> 8, w = line & 255;
            base = b * (T * T * D) + w * D;
            sp   = T * D;
        } else {
            base = line * (T * D);
            sp   = D;
        }
    };

    auto stage_x_chunk = [&](int t, int q) {   // 16 rows -> XF slot (q&1)
        int base, sp, p0; tile_base(t, base, sp, p0);
        uint32_t dst = sb + OFF_XF + (uint32_t)(q & 1) * 8192;
#pragma unroll
        for (int u = 0; u < 2; u++) {
            int s = tid + u * 256;
            int rl = s >> 5, c4 = s & 31;
            cpa16(dst + (uint32_t)s * 16,
                  x + base + (p0 + q * 16 + rl) * sp + c4 * 4, 16);
        }
    };
    auto convert_chunk = [&](int q) {          // XF slot -> XH/XL bf16 split
        const char* src = sm + OFF_XF + (q & 1) * 8192;
#pragma unroll
        for (int u = 0; u < 2; u++) {
            int s = tid + u * 256;
            int rl = s >> 5, c4 = s & 31;
            float4 v = *(const float4*)(src + s * 16);
            ull hw, lw; split4(v, hw, lw);
            uint32_t off = (uint32_t)(q * 16 + rl) * 272 + (uint32_t)c4 * 8;
            *(ull*)(sm + OFF_XH + off) = hw;
            *(ull*)(sm + OFF_XL + off) = lw;
        }
    };
    auto xpipe = [&](int t) {                  // chunk0 must be committed
#pragma unroll 1
        for (int q = 0; q < 8; q++) {
            if (q < 7) { stage_x_chunk(t, q + 1); cpa_commit(); cpa_wait1(); }
            else       { cpa_wait0(); }
            convert_chunk(q);
            __syncthreads();                   // protect slot reuse
        }
    };
    auto stage_kv = [&](int t) {
        int base, sp, p0; tile_base(t, base, sp, p0);
        for (int s = tid; s < 130 * 32; s += 256) {
            int row = s >> 5, c4 = s & 31;
            int gp = p0 - 1 + row;
            bool ok = (gp >= 0) && (gp < T);
            cpa16(sb + OFF_KF + (uint32_t)(row * KF_PITCH + c4 * 4) * 4,
                  kv + base + (ok ? gp * sp : 0) + c4 * 4, ok ? 16 : 0);
        }
    };

    // per-thread ldmatrix base offsets
    uint32_t aoffH[2], aoffL[2], boffH[4], boffL[4];
#pragma unroll
    for (int mi = 0; mi < 2; mi++) {
        uint32_t b = (uint32_t)(32 * rg + 16 * mi + (lane & 15)) * 272
                   + ((uint32_t)(lane >> 4) << 4);
        aoffH[mi] = sb + OFF_XH + b;
        aoffL[mi] = sb + OFF_XL + b;
    }
#pragma unroll
    for (int ng = 0; ng < 4; ng++) {
        uint32_t b = (uint32_t)(64 * cg + 16 * ng + ((lane >> 4) << 3) + (lane & 7)) * 272
                   + (((uint32_t)(lane >> 3) & 1) << 4);
        boffH[ng] = sb + OFF_MH + b;
        boffL[ng] = sb + OFF_ML + b;
    }

    const int t0 = blockIdx.x, stride = gridDim.x;

    // ---- prologue ----
    stage_x_chunk(t0, 0); cpa_commit();
    xpipe(t0);
    stage_kv(t0); cpa_commit();
    __syncthreads();

    for (int t = t0; t < NTILES; t += stride) {
        const int tn = t + stride;
        const bool hn = tn < NTILES;
        int base, sp, p0; tile_base(t, base, sp, p0);

        // ---- GEMM: acc = Xh@Mh + Xh@Ml + Xl@Mh ----
        float acc[2][8][4];
#pragma unroll
        for (int mi = 0; mi < 2; mi++)
#pragma unroll
            for (int nt = 0; nt < 8; nt++)
#pragma unroll
                for (int u = 0; u < 4; u++) acc[mi][nt][u] = 0.f;

#pragma unroll 1
        for (int ks = 0; ks < 8; ks++) {
            const uint32_t ko = (uint32_t)ks * 32;
            uint32_t ah[2][4], al[2][4], bh[4][4], bl[4][4];
#pragma unroll
            for (int mi = 0; mi < 2; mi++) {
                ldsm4(ah[mi], aoffH[mi] + ko);
                ldsm4(al[mi], aoffL[mi] + ko);
            }
#pragma unroll
            for (int ng = 0; ng < 4; ng++) {
                ldsm4(bh[ng], boffH[ng] + ko);
                ldsm4(bl[ng], boffL[ng] + ko);
            }
#pragma unroll
            for (int mi = 0; mi < 2; mi++)
#pragma unroll
                for (int ng = 0; ng < 4; ng++) {
                    mmabf(acc[mi][2 * ng],     ah[mi], bh[ng][0], bh[ng][1]);
                    mmabf(acc[mi][2 * ng + 1], ah[mi], bh[ng][2], bh[ng][3]);
                    mmabf(acc[mi][2 * ng],     ah[mi], bl[ng][0], bl[ng][1]);
                    mmabf(acc[mi][2 * ng + 1], ah[mi], bl[ng][2], bl[ng][3]);
                    mmabf(acc[mi][2 * ng],     al[mi], bh[ng][0], bh[ng][1]);
                    mmabf(acc[mi][2 * ng + 1], al[mi], bh[ng][2], bh[ng][3]);
                }
        }

        cpa_wait0();     // KV(t) landed (only pending group)

        // ---- banded dots from register accumulators ----
        {
            const float* KF = (const float*)(sm + OFF_KF);
            float prt[12];
#pragma unroll
            for (int mi = 0; mi < 2; mi++)
#pragma unroll
                for (int h = 0; h < 2; h++) {
                    int r = 32 * rg + 16 * mi + 8 * h + qrow;
#pragma unroll
                    for (int dd = 0; dd < 3; dd++) {
                        float s = 0.f;
#pragma unroll
                        for (int nt = 0; nt < 8; nt++) {
                            int c = 64 * cg + 8 * nt + 2 * qc;
                            float2 kp = *(const float2*)(KF + (r + dd) * KF_PITCH + c);
                            s = fmaf(acc[mi][nt][2 * h],     kp.x, s);
                            s = fmaf(acc[mi][nt][2 * h + 1], kp.y, s);
                        }
                        prt[(mi * 2 + h) * 3 + dd] = s;
                    }
                }
#pragma unroll
            for (int i = 0; i < 12; i++) {
                float v = prt[i];
                v += __shfl_xor_sync(0xffffffffu, v, 1);
                v += __shfl_xor_sync(0xffffffffu, v, 2);
                prt[i] = v;
            }
            if (qc == 0) {
                float* PT = (float*)(sm + OFF_PT);
#pragma unroll
                for (int mi = 0; mi < 2; mi++)
#pragma unroll
                    for (int h = 0; h < 2; h++) {
                        int r = 32 * rg + 16 * mi + 8 * h + qrow;
#pragma unroll
                        for (int dd = 0; dd < 3; dd++)
                            PT[(dd * 128 + r) * 2 + cg] = prt[(mi * 2 + h) * 3 + dd];
                    }
            }
        }
        __syncthreads();

        // ---- exact band softmax ----
        if (tid < 128) {
            const float* PT = (const float*)(sm + OFF_PT);
            float* DT = (float*)(sm + OFF_DT);
            int pos = tid, gp = p0 + pos;
            float d0 = PT[(0 * 128 + pos) * 2] + PT[(0 * 128 + pos) * 2 + 1];
            float d1 = PT[(1 * 128 + pos) * 2] + PT[(1 * 128 + pos) * 2 + 1];
            float d2 = PT[(2 * 128 + pos) * 2] + PT[(2 * 128 + pos) * 2 + 1];
            float m = d1;
            if (gp > 0)     m = fmaxf(m, d0);
            if (gp < T - 1) m = fmaxf(m, d2);
            float w0 = (gp > 0)     ? __expf(d0 - m) : 0.f;
            float w1 = __expf(d1 - m);
            float w2 = (gp < T - 1) ? __expf(d2 - m) : 0.f;
            float inv = 1.f / (w0 + w1 + w2);
            DT[pos * 4 + 0] = w0 * inv;
            DT[pos * 4 + 1] = w1 * inv;
            DT[pos * 4 + 2] = w2 * inv;
        }
        __syncthreads();

        // ---- weighted kv sum -> global out (AXIS_H accumulates) ----
        {
            const float* DT = (const float*)(sm + OFF_DT);
            const float4* kf4 = (const float4*)(sm + OFF_KF);
            int pos = tid >> 1, hf = tid & 1;
            float a0 = DT[pos * 4 + 0];
            float a1 = DT[pos * 4 + 1];
            float a2 = DT[pos * 4 + 2];
            const float4* k0 = kf4 + (pos + 0) * (KF_PITCH / 4);
            const float4* k1 = kf4 + (pos + 1) * (KF_PITCH / 4);
            const float4* k2 = kf4 + (pos + 2) * (KF_PITCH / 4);
            float4* go = (float4*)(out + base + (p0 + pos) * sp);
#pragma unroll
            for (int u = 0; u < 16; u++) {
                int c4 = hf * 16 + u;
                float4 v0 = k0[c4], v1 = k1[c4], v2 = k2[c4];
                float4 r;
                r.x = a0 * v0.x + a1 * v1.x + a2 * v2.x;
                r.y = a0 * v0.y + a1 * v1.y + a2 * v2.y;
                r.z = a0 * v0.z + a1 * v1.z + a2 * v2.z;
                r.w = a0 * v0.w + a1 * v1.w + a2 * v2.w;
                if (AXIS_H) {
                    float4 o = go[c4];
                    r.x += o.x; r.y += o.y; r.z += o.z; r.w += o.w;
                }
                go[c4] = r;
            }
        }
        __syncthreads();   // KF/DT reads done; XF overlay free

        if (hn) {
            stage_x_chunk(tn, 0); cpa_commit();
            xpipe(tn);                       // fills XH/XL(tn)
            stage_kv(tn); cpa_commit();      // overlaps next GEMM
        }
        __syncthreads();
    }
}

// ---------------------------------------------------------------------------
extern "C" void kernel_launch(void* const* d_in, const int* in_sizes, int n_in,
                              void* d_out, int out_size) {
    const float* x    = (const float*)d_in[0];
    const float* kv   = (const float*)d_in[1];
    const float* Wq_h = (const float*)d_in[2];
    const float* Wk_h = (const float*)d_in[3];
    const float* Wq_w = (const float*)d_in[4];
    const float* Wk_w = (const float*)d_in[5];
    float* out = (float*)d_out;

    cudaFuncSetAttribute(axial_mma<0>,
                         cudaFuncAttributeMaxDynamicSharedMemorySize, SMEM_TOTAL);
    cudaFuncSetAttribute(axial_mma<1>,
                         cudaFuncAttributeMaxDynamicSharedMemorySize, SMEM_TOTAL);

    int nsm = 148;
    cudaDeviceGetAttribute(&nsm, cudaDevAttrMultiProcessorCount, 0);
    if (nsm <= 0) nsm = 148;
    if (nsm > NTILES) nsm = NTILES;

    compute_M_kernel<<<dim3(128, 2), 128>>>(Wq_h, Wk_h, Wq_w, Wk_w);
    axial_mma<0><<<nsm, 256, SMEM_TOTAL>>>(x, kv, out);   // width: writes
    axial_mma<1><<<nsm, 256, SMEM_TOTAL>>>(x, kv, out);   // height: accumulates
}

// round 7
// speedup vs baseline: 2.3964x; 1.1010x over previous
#include <cuda_runtime.h>
#include <cuda_bf16.h>
#include <cstdint>

#define D 128
#define T 256
#define NTILES 2048          // per axis: 1024 lines * 2 tiles of 128
#define SCALE 0.08838834764831845f   // 128^-0.5
#define KF_PITCH 140         // fp32 KV row pitch: 140 mod 32 = 12 -> injective banks
#define PITCH 136            // bf16 row pitch for X/M tiles (272B rows)

typedef unsigned long long ull;

// Per-axis precomputed M^T (fp32): g_MT[c*128 + k] = (Wq^T Wk)[k,c] * SCALE
__device__ float g_MT_h[D * D];
__device__ float g_MT_w[D * D];

// ---- smem byte layout ----
#define OFF_MH 0                            // bf16 M hi [128c][PITCH]
#define OFF_ML (OFF_MH + 34816)             // bf16 M lo
#define OFF_XH (OFF_ML + 34816)             // bf16 X hi [128r][PITCH]
#define OFF_XL (OFF_XH + 34816)             // bf16 X lo
#define OFF_KF (OFF_XL + 34816)             // fp32 KV: 130 x 140
#define OFF_PT (OFF_KF + 130 * KF_PITCH * 4)  // partials [3][128][2] fp32
#define OFF_DT (OFF_PT + 3072)              // weights  [128][4] fp32
#define SMEM_TOTAL (OFF_DT + 2048)          // 217184 B

// ---------------------------------------------------------------------------
__device__ __forceinline__ uint32_t smem_u32(const void* p) {
    uint32_t a;
    asm("{ .reg .u64 t; cvta.to.shared.u64 t, %1; cvt.u32.u64 %0, t; }"
        : "=r"(a) : "l"(p));
    return a;
}
__device__ __forceinline__ void cpa16(uint32_t dst, const void* src, int srcsz) {
    asm volatile("cp.async.cg.shared.global [%0], [%1], 16, %2;"
                 :: "r"(dst), "l"(src), "r"(srcsz));
}
__device__ __forceinline__ void cpa_commit() {
    asm volatile("cp.async.commit_group;");
}
__device__ __forceinline__ void cpa_wait0() {
    asm volatile("cp.async.wait_group 0;" ::: "memory");
}
__device__ __forceinline__ void ldsm4(uint32_t* r, uint32_t a) {
    asm volatile("ldmatrix.sync.aligned.m8n8.x4.shared.b16 {%0,%1,%2,%3}, [%4];"
                 : "=r"(r[0]), "=r"(r[1]), "=r"(r[2]), "=r"(r[3]) : "r"(a));
}
__device__ __forceinline__ void mmabf(float* d, const uint32_t* a,
                                      uint32_t b0, uint32_t b1) {
    asm volatile(
        "mma.sync.aligned.m16n8k16.row.col.f32.bf16.bf16.f32 "
        "{%0,%1,%2,%3},{%4,%5,%6,%7},{%8,%9},{%0,%1,%2,%3};"
        : "+f"(d[0]), "+f"(d[1]), "+f"(d[2]), "+f"(d[3])
        : "r"(a[0]), "r"(a[1]), "r"(a[2]), "r"(a[3]), "r"(b0), "r"(b1));
}

// fp32 -> (bf16 hi, bf16 lo) split, 4 elems -> two 8B words
__device__ __forceinline__ void split4(float4 v, ull& hw, ull& lw) {
    __nv_bfloat162 h0 = __floats2bfloat162_rn(v.x, v.y);
    __nv_bfloat162 h1 = __floats2bfloat162_rn(v.z, v.w);
    float2 f0 = __bfloat1622float2(h0);
    float2 f1 = __bfloat1622float2(h1);
    __nv_bfloat162 l0 = __floats2bfloat162_rn(v.x - f0.x, v.y - f0.y);
    __nv_bfloat162 l1 = __floats2bfloat162_rn(v.z - f1.x, v.w - f1.y);
    unsigned uh0 = *(unsigned*)&h0, uh1 = *(unsigned*)&h1;
    unsigned ul0 = *(unsigned*)&l0, ul1 = *(unsigned*)&l1;
    hw = (ull)uh0 | ((ull)uh1 << 32);
    lw = (ull)ul0 | ((ull)ul1 << 32);
}

// ---------------------------------------------------------------------------
// Kernel 1: M^T[c][k] = sum_e Wq[e,k] * Wk[e,c] * SCALE  (per axis)
// ---------------------------------------------------------------------------
__global__ void compute_M_kernel(const float* __restrict__ Wq_h,
                                 const float* __restrict__ Wk_h,
                                 const float* __restrict__ Wq_w,
                                 const float* __restrict__ Wk_w) {
    int k = blockIdx.x, c = threadIdx.x, axis = blockIdx.y;
    const float* Wq = axis ? Wq_h : Wq_w;
    const float* Wk = axis ? Wk_h : Wk_w;
    float*       MT = axis ? g_MT_h : g_MT_w;
    __shared__ float sq[D];
    sq[c] = Wq[c * D + k];
    __syncthreads();
    float s = 0.f;
#pragma unroll 8
    for (int e = 0; e < D; e++) s = fmaf(sq[e], Wk[e * D + c], s);
    MT[c * D + k] = s * SCALE;
}

// ---------------------------------------------------------------------------
// Kernel 2: persistent HMMA fused axial attention (one axis per launch)
// ---------------------------------------------------------------------------
template <int AXIS_H>
__global__ __launch_bounds__(256, 1)
void axial_mma(const float* __restrict__ x, const float* __restrict__ kv,
               float* __restrict__ out) {
    extern __shared__ char sm[];
    const uint32_t sb = smem_u32(sm);
    const int tid = threadIdx.x, wid = tid >> 5, lane = tid & 31;
    const int rg = wid >> 1, cg = wid & 1;       // row-group, col-group
    const int qrow = lane >> 2, qc = lane & 3;

    // ---- stage + split M^T once per CTA ----
    {
        const float4* MT4 = (const float4*)(AXIS_H ? g_MT_h : g_MT_w);
        for (int s = tid; s < D * 32; s += 256) {
            int r = s >> 5, c8 = (s & 31) * 8;
            float4 v = MT4[s];
            ull hw, lw; split4(v, hw, lw);
            *(ull*)(sm + OFF_MH + r * 272 + c8) = hw;
            *(ull*)(sm + OFF_ML + r * 272 + c8) = lw;
        }
    }

    auto tile_base = [](int t, int& base, int& sp, int& p0) {
        int line = t >> 1;
        p0 = (t & 1) * 128;
        if (AXIS_H) {
            int b = line >> 8, w = line & 255;
            base = b * (T * T * D) + w * D;
            sp   = T * D;
        } else {
            base = line * (T * D);
            sp   = D;
        }
    };

    // X staging: half = 64 rows = 2048 float4 -> 8 float4/thread
    auto ldg_half = [&](int t, int half, float4* xa) {
        int base, sp, p0; tile_base(t, base, sp, p0);
#pragma unroll
        for (int u = 0; u < 8; u++) {
            int s = tid + u * 256;
            int rl = (s >> 5) + half * 64, c4 = s & 31;
            xa[u] = __ldg((const float4*)(x + base + (p0 + rl) * sp + c4 * 4));
        }
    };
    auto sts_half = [&](int half, const float4* xa) {
#pragma unroll
        for (int u = 0; u < 8; u++) {
            int s = tid + u * 256;
            int rl = (s >> 5) + half * 64, c4 = s & 31;
            ull hw, lw; split4(xa[u], hw, lw);
            uint32_t off = (uint32_t)rl * 272 + (uint32_t)c4 * 8;
            *(ull*)(sm + OFF_XH + off) = hw;
            *(ull*)(sm + OFF_XL + off) = lw;
        }
    };
    auto stage_kv = [&](int t) {
        int base, sp, p0; tile_base(t, base, sp, p0);
        for (int s = tid; s < 130 * 32; s += 256) {
            int row = s >> 5, c4 = s & 31;
            int gp = p0 - 1 + row;
            bool ok = (gp >= 0) && (gp < T);
            cpa16(sb + OFF_KF + (uint32_t)(row * KF_PITCH + c4 * 4) * 4,
                  kv + base + (ok ? gp * sp : 0) + c4 * 4, ok ? 16 : 0);
        }
        cpa_commit();
    };

    // per-thread ldmatrix base offsets
    uint32_t aoffH[2], aoffL[2], boffH[4], boffL[4];
#pragma unroll
    for (int mi = 0; mi < 2; mi++) {
        uint32_t b = (uint32_t)(32 * rg + 16 * mi + (lane & 15)) * 272
                   + ((uint32_t)(lane >> 4) << 4);
        aoffH[mi] = sb + OFF_XH + b;
        aoffL[mi] = sb + OFF_XL + b;
    }
#pragma unroll
    for (int ng = 0; ng < 4; ng++) {
        uint32_t b = (uint32_t)(64 * cg + 16 * ng + ((lane >> 4) << 3) + (lane & 7)) * 272
                   + (((uint32_t)(lane >> 3) & 1) << 4);
        boffH[ng] = sb + OFF_MH + b;
        boffL[ng] = sb + OFF_ML + b;
    }

    const int t0 = blockIdx.x, stride = gridDim.x;

    // ---- prologue: X(t0) + KV(t0) ----
    {
        float4 xa[8];
        ldg_half(t0, 0, xa); sts_half(0, xa);
        ldg_half(t0, 1, xa); sts_half(1, xa);
        stage_kv(t0);
    }
    __syncthreads();

    for (int t = t0; t < NTILES; t += stride) {
        const int tn = t + stride;
        const bool hn = tn < NTILES;
        int base, sp, p0; tile_base(t, base, sp, p0);

        // prefetch next tile's X half A into registers (hidden under GEMM)
        float4 xa[8];
        if (hn) ldg_half(tn, 0, xa);

        // ---- GEMM: acc = Xh@Mh + Xh@Ml + Xl@Mh ----
        float acc[2][8][4];
#pragma unroll
        for (int mi = 0; mi < 2; mi++)
#pragma unroll
            for (int nt = 0; nt < 8; nt++)
#pragma unroll
                for (int u = 0; u < 4; u++) acc[mi][nt][u] = 0.f;

#pragma unroll 1
        for (int ks = 0; ks < 8; ks++) {
            const uint32_t ko = (uint32_t)ks * 32;
            uint32_t ah[2][4], al[2][4], bh[4][4], bl[4][4];
#pragma unroll
            for (int mi = 0; mi < 2; mi++) {
                ldsm4(ah[mi], aoffH[mi] + ko);
                ldsm4(al[mi], aoffL[mi] + ko);
            }
#pragma unroll
            for (int ng = 0; ng < 4; ng++) {
                ldsm4(bh[ng], boffH[ng] + ko);
                ldsm4(bl[ng], boffL[ng] + ko);
            }
#pragma unroll
            for (int mi = 0; mi < 2; mi++)
#pragma unroll
                for (int ng = 0; ng < 4; ng++) {
                    mmabf(acc[mi][2 * ng],     ah[mi], bh[ng][0], bh[ng][1]);
                    mmabf(acc[mi][2 * ng + 1], ah[mi], bh[ng][2], bh[ng][3]);
                    mmabf(acc[mi][2 * ng],     ah[mi], bl[ng][0], bl[ng][1]);
                    mmabf(acc[mi][2 * ng + 1], ah[mi], bl[ng][2], bl[ng][3]);
                    mmabf(acc[mi][2 * ng],     al[mi], bh[ng][0], bh[ng][1]);
                    mmabf(acc[mi][2 * ng + 1], al[mi], bh[ng][2], bh[ng][3]);
                }
        }

        cpa_wait0();
        __syncthreads();     // KV(t) visible to all threads

        // ---- banded dots from register accumulators ----
        {
            const float* KF = (const float*)(sm + OFF_KF);
            float prt[12];
#pragma unroll
            for (int mi = 0; mi < 2; mi++)
#pragma unroll
                for (int h = 0; h < 2; h++) {
                    int r = 32 * rg + 16 * mi + 8 * h + qrow;
#pragma unroll
                    for (int dd = 0; dd < 3; dd++) {
                        float s = 0.f;
#pragma unroll
                        for (int nt = 0; nt < 8; nt++) {
                            int c = 64 * cg + 8 * nt + 2 * qc;
                            float2 kp = *(const float2*)(KF + (r + dd) * KF_PITCH + c);
                            s = fmaf(acc[mi][nt][2 * h],     kp.x, s);
                            s = fmaf(acc[mi][nt][2 * h + 1], kp.y, s);
                        }
                        prt[(mi * 2 + h) * 3 + dd] = s;
                    }
                }
#pragma unroll
            for (int i = 0; i < 12; i++) {
                float v = prt[i];
                v += __shfl_xor_sync(0xffffffffu, v, 1);
                v += __shfl_xor_sync(0xffffffffu, v, 2);
                prt[i] = v;
            }
            if (qc == 0) {
                float* PT = (float*)(sm + OFF_PT);
#pragma unroll
                for (int mi = 0; mi < 2; mi++)
#pragma unroll
                    for (int h = 0; h < 2; h++) {
                        int r = 32 * rg + 16 * mi + 8 * h + qrow;
#pragma unroll
                        for (int dd = 0; dd < 3; dd++)
                            PT[(dd * 128 + r) * 2 + cg] = prt[(mi * 2 + h) * 3 + dd];
                    }
            }
        }
        __syncthreads();     // PT ready; XH/XL free (GEMM reads done)

        // ---- store X(tn) half A; prefetch half B; softmax ----
        float4 xb[8];
        if (hn) {
            sts_half(0, xa);
            ldg_half(tn, 1, xb);
        }
        if (tid < 128) {
            const float* PT = (const float*)(sm + OFF_PT);
            float* DT = (float*)(sm + OFF_DT);
            int pos = tid, gp = p0 + pos;
            float d0 = PT[(0 * 128 + pos) * 2] + PT[(0 * 128 + pos) * 2 + 1];
            float d1 = PT[(1 * 128 + pos) * 2] + PT[(1 * 128 + pos) * 2 + 1];
            float d2 = PT[(2 * 128 + pos) * 2] + PT[(2 * 128 + pos) * 2 + 1];
            float m = d1;
            if (gp > 0)     m = fmaxf(m, d0);
            if (gp < T - 1) m = fmaxf(m, d2);
            float w0 = (gp > 0)     ? __expf(d0 - m) : 0.f;
            float w1 = __expf(d1 - m);
            float w2 = (gp < T - 1) ? __expf(d2 - m) : 0.f;
            float inv = 1.f / (w0 + w1 + w2);
            DT[pos * 4 + 0] = w0 * inv;
            DT[pos * 4 + 1] = w1 * inv;
            DT[pos * 4 + 2] = w2 * inv;
        }
        __syncthreads();     // DT ready

        // ---- weighted kv sum -> global out (AXIS_H accumulates) ----
        {
            const float* DT = (const float*)(sm + OFF_DT);
            const float4* kf4 = (const float4*)(sm + OFF_KF);
            int pos = tid >> 1, hf = tid & 1;
            float a0 = DT[pos * 4 + 0];
            float a1 = DT[pos * 4 + 1];
            float a2 = DT[pos * 4 + 2];
            const float4* k0 = kf4 + (pos + 0) * (KF_PITCH / 4);
            const float4* k1 = kf4 + (pos + 1) * (KF_PITCH / 4);
            const float4* k2 = kf4 + (pos + 2) * (KF_PITCH / 4);
            float4* go = (float4*)(out + base + (p0 + pos) * sp);
#pragma unroll
            for (int u = 0; u < 16; u++) {
                int c4 = hf * 16 + u;
                float4 v0 = k0[c4], v1 = k1[c4], v2 = k2[c4];
                float4 r;
                r.x = a0 * v0.x + a1 * v1.x + a2 * v2.x;
                r.y = a0 * v0.y + a1 * v1.y + a2 * v2.y;
                r.z = a0 * v0.z + a1 * v1.z + a2 * v2.z;
                r.w = a0 * v0.w + a1 * v1.w + a2 * v2.w;
                if (AXIS_H) {
                    float4 o = go[c4];
                    r.x += o.x; r.y += o.y; r.z += o.z; r.w += o.w;
                }
                go[c4] = r;
            }
        }

        if (hn) sts_half(1, xb);    // X(tn) half B (LDG latency hidden above)
        __syncthreads();            // KF reads done; XH/XL(tn) complete

        if (hn) stage_kv(tn);       // async; waited after GEMM(tn)
    }
}

// ---------------------------------------------------------------------------
extern "C" void kernel_launch(void* const* d_in, const int* in_sizes, int n_in,
                              void* d_out, int out_size) {
    const float* x    = (const float*)d_in[0];
    const float* kv   = (const float*)d_in[1];
    const float* Wq_h = (const float*)d_in[2];
    const float* Wk_h = (const float*)d_in[3];
    const float* Wq_w = (const float*)d_in[4];
    const float* Wk_w = (const float*)d_in[5];
    float* out = (float*)d_out;

    cudaFuncSetAttribute(axial_mma<0>,
                         cudaFuncAttributeMaxDynamicSharedMemorySize, SMEM_TOTAL);
    cudaFuncSetAttribute(axial_mma<1>,
                         cudaFuncAttributeMaxDynamicSharedMemorySize, SMEM_TOTAL);

    int nsm = 148;
    cudaDeviceGetAttribute(&nsm, cudaDevAttrMultiProcessorCount, 0);
    if (nsm <= 0) nsm = 148;
    if (nsm > NTILES) nsm = NTILES;

    compute_M_kernel<<<dim3(128, 2), 128>>>(Wq_h, Wk_h, Wq_w, Wk_w);
    axial_mma<0><<<nsm, 256, SMEM_TOTAL>>>(x, kv, out);   // width: writes
    axial_mma<1><<<nsm, 256, SMEM_TOTAL>>>(x, kv, out);   // height: accumulates
}

// round 8
// speedup vs baseline: 3.3606x; 1.4023x over previous
#include <cuda_runtime.h>
#include <cuda_fp16.h>
#include <cstdint>

#define D 128
#define T 256
#define NTILES 2048          // per axis: 1024 lines * 2 tiles of 128
#define SCALE 0.08838834764831845f   // 128^-0.5
#define KF_PITCH 140         // fp32 KV row pitch: injective bank mapping
#define PITCH 136            // fp16 row pitch for X/M tiles (272B rows)

typedef unsigned long long ull;

// Per-axis precomputed M^T (fp32): g_MT[c*128 + k] = (Wq^T Wk)[k,c] * SCALE
__device__ float g_MT_h[D * D];
__device__ float g_MT_w[D * D];

// ---- smem byte layout ----
#define OFF_MH 0                              // fp16 M [128c][PITCH]
#define OFF_XH (OFF_MH + 34816)               // fp16 X [128r][PITCH]
#define OFF_KF (OFF_XH + 34816)               // fp32 KV: 130 x 140
#define OFF_PT (OFF_KF + 130 * KF_PITCH * 4)  // partials [3][128][2] fp32
#define OFF_DT (OFF_PT + 3072)                // weights  [128][4] fp32
#define SMEM_TOTAL (OFF_DT + 2048)            // 147552 B

// ---------------------------------------------------------------------------
__device__ __forceinline__ uint32_t smem_u32(const void* p) {
    uint32_t a;
    asm("{ .reg .u64 t; cvta.to.shared.u64 t, %1; cvt.u32.u64 %0, t; }"
        : "=r"(a) : "l"(p));
    return a;
}
__device__ __forceinline__ void cpa16(uint32_t dst, const void* src, int srcsz) {
    asm volatile("cp.async.cg.shared.global [%0], [%1], 16, %2;"
                 :: "r"(dst), "l"(src), "r"(srcsz));
}
__device__ __forceinline__ void cpa_commit() {
    asm volatile("cp.async.commit_group;");
}
__device__ __forceinline__ void cpa_wait0() {
    asm volatile("cp.async.wait_group 0;" ::: "memory");
}
__device__ __forceinline__ void ldsm4(uint32_t* r, uint32_t a) {
    asm volatile("ldmatrix.sync.aligned.m8n8.x4.shared.b16 {%0,%1,%2,%3}, [%4];"
                 : "=r"(r[0]), "=r"(r[1]), "=r"(r[2]), "=r"(r[3]) : "r"(a));
}
__device__ __forceinline__ void mmah(float* d, const uint32_t* a,
                                     uint32_t b0, uint32_t b1) {
    asm volatile(
        "mma.sync.aligned.m16n8k16.row.col.f32.f16.f16.f32 "
        "{%0,%1,%2,%3},{%4,%5,%6,%7},{%8,%9},{%0,%1,%2,%3};"
        : "+f"(d[0]), "+f"(d[1]), "+f"(d[2]), "+f"(d[3])
        : "r"(a[0]), "r"(a[1]), "r"(a[2]), "r"(a[3]), "r"(b0), "r"(b1));
}
__device__ __forceinline__ ull pack4h(float4 v) {
    __half2 h0 = __floats2half2_rn(v.x, v.y);
    __half2 h1 = __floats2half2_rn(v.z, v.w);
    unsigned u0 = *(unsigned*)&h0, u1 = *(unsigned*)&h1;
    return (ull)u0 | ((ull)u1 << 32);
}

// ---------------------------------------------------------------------------
// Kernel 1: M^T[c][k] = sum_e Wq[e,k] * Wk[e,c] * SCALE  (per axis)
// ---------------------------------------------------------------------------
__global__ void compute_M_kernel(const float* __restrict__ Wq_h,
                                 const float* __restrict__ Wk_h,
                                 const float* __restrict__ Wq_w,
                                 const float* __restrict__ Wk_w) {
    int k = blockIdx.x, c = threadIdx.x, axis = blockIdx.y;
    const float* Wq = axis ? Wq_h : Wq_w;
    const float* Wk = axis ? Wk_h : Wk_w;
    float*       MT = axis ? g_MT_h : g_MT_w;
    __shared__ float sq[D];
    sq[c] = Wq[c * D + k];
    __syncthreads();
    float s = 0.f;
#pragma unroll 8
    for (int e = 0; e < D; e++) s = fmaf(sq[e], Wk[e * D + c], s);
    MT[c * D + k] = s * SCALE;
}

// ---------------------------------------------------------------------------
// Kernel 2: persistent HMMA fused axial attention (one axis per launch)
// ---------------------------------------------------------------------------
template <int AXIS_H>
__global__ __launch_bounds__(256, 1)
void axial_mma(const float* __restrict__ x, const float* __restrict__ kv,
               float* __restrict__ out) {
    extern __shared__ char sm[];
    const uint32_t sb = smem_u32(sm);
    const int tid = threadIdx.x, wid = tid >> 5, lane = tid & 31;
    const int rg = wid >> 1, cg = wid & 1;       // row-group, col-group
    const int qrow = lane >> 2, qc = lane & 3;

    // ---- stage M^T (fp16) once per CTA ----
    {
        const float4* MT4 = (const float4*)(AXIS_H ? g_MT_h : g_MT_w);
        for (int s = tid; s < D * 32; s += 256) {
            int r = s >> 5, c8 = (s & 31) * 8;
            *(ull*)(sm + OFF_MH + r * 272 + c8) = pack4h(MT4[s]);
        }
    }

    auto tile_base = [](int t, int& base, int& sp, int& p0) {
        int line = t >> 1;
        p0 = (t & 1) * 128;
        if (AXIS_H) {
            int b = line >> 8, w = line & 255;
            base = b * (T * T * D) + w * D;
            sp   = T * D;
        } else {
            base = line * (T * D);
            sp   = D;
        }
    };

    // X staging: half = 64 rows = 2048 float4 -> 8 float4/thread
    auto ldg_half = [&](int t, int half, float4* xa) {
        int base, sp, p0; tile_base(t, base, sp, p0);
#pragma unroll
        for (int u = 0; u < 8; u++) {
            int s = tid + u * 256;
            int rl = (s >> 5) + half * 64, c4 = s & 31;
            xa[u] = __ldg((const float4*)(x + base + (p0 + rl) * sp + c4 * 4));
        }
    };
    auto sts_half = [&](int half, const float4* xa) {
#pragma unroll
        for (int u = 0; u < 8; u++) {
            int s = tid + u * 256;
            int rl = (s >> 5) + half * 64, c4 = s & 31;
            *(ull*)(sm + OFF_XH + (uint32_t)rl * 272 + (uint32_t)c4 * 8) =
                pack4h(xa[u]);
        }
    };
    auto stage_kv = [&](int t) {
        int base, sp, p0; tile_base(t, base, sp, p0);
        for (int s = tid; s < 130 * 32; s += 256) {
            int row = s >> 5, c4 = s & 31;
            int gp = p0 - 1 + row;
            bool ok = (gp >= 0) && (gp < T);
            cpa16(sb + OFF_KF + (uint32_t)(row * KF_PITCH + c4 * 4) * 4,
                  kv + base + (ok ? gp * sp : 0) + c4 * 4, ok ? 16 : 0);
        }
        cpa_commit();
    };

    // per-thread ldmatrix base offsets
    uint32_t aoff[2], boff[4];
#pragma unroll
    for (int mi = 0; mi < 2; mi++) {
        aoff[mi] = sb + OFF_XH
                 + (uint32_t)(32 * rg + 16 * mi + (lane & 15)) * 272
                 + ((uint32_t)(lane >> 4) << 4);
    }
#pragma unroll
    for (int ng = 0; ng < 4; ng++) {
        boff[ng] = sb + OFF_MH
                 + (uint32_t)(64 * cg + 16 * ng + ((lane >> 4) << 3) + (lane & 7)) * 272
                 + (((uint32_t)(lane >> 3) & 1) << 4);
    }

    const int t0 = blockIdx.x, stride = gridDim.x;

    // ---- prologue: X(t0) + KV(t0) ----
    {
        float4 xa[8];
        ldg_half(t0, 0, xa); sts_half(0, xa);
        ldg_half(t0, 1, xa); sts_half(1, xa);
        stage_kv(t0);
    }
    __syncthreads();

    for (int t = t0; t < NTILES; t += stride) {
        const int tn = t + stride;
        const bool hn = tn < NTILES;
        int base, sp, p0; tile_base(t, base, sp, p0);

        // prefetch next tile's X half A into registers (hidden under GEMM)
        float4 xa[8];
        if (hn) ldg_half(tn, 0, xa);

        // ---- GEMM: acc = X(fp16) @ M(fp16), fp32 accumulate ----
        float acc[2][8][4];
#pragma unroll
        for (int mi = 0; mi < 2; mi++)
#pragma unroll
            for (int nt = 0; nt < 8; nt++)
#pragma unroll
                for (int u = 0; u < 4; u++) acc[mi][nt][u] = 0.f;

#pragma unroll 1
        for (int ks = 0; ks < 8; ks++) {
            const uint32_t ko = (uint32_t)ks * 32;
            uint32_t ah[2][4], bh[4][4];
#pragma unroll
            for (int mi = 0; mi < 2; mi++) ldsm4(ah[mi], aoff[mi] + ko);
#pragma unroll
            for (int ng = 0; ng < 4; ng++) ldsm4(bh[ng], boff[ng] + ko);
#pragma unroll
            for (int mi = 0; mi < 2; mi++)
#pragma unroll
                for (int ng = 0; ng < 4; ng++) {
                    mmah(acc[mi][2 * ng],     ah[mi], bh[ng][0], bh[ng][1]);
                    mmah(acc[mi][2 * ng + 1], ah[mi], bh[ng][2], bh[ng][3]);
                }
        }

        cpa_wait0();
        __syncthreads();     // KV(t) visible to all threads

        // ---- banded dots from register accumulators ----
        {
            const float* KF = (const float*)(sm + OFF_KF);
            float prt[12];
#pragma unroll
            for (int mi = 0; mi < 2; mi++)
#pragma unroll
                for (int h = 0; h < 2; h++) {
                    int r = 32 * rg + 16 * mi + 8 * h + qrow;
#pragma unroll
                    for (int dd = 0; dd < 3; dd++) {
                        float s = 0.f;
#pragma unroll
                        for (int nt = 0; nt < 8; nt++) {
                            int c = 64 * cg + 8 * nt + 2 * qc;
                            float2 kp = *(const float2*)(KF + (r + dd) * KF_PITCH + c);
                            s = fmaf(acc[mi][nt][2 * h],     kp.x, s);
                            s = fmaf(acc[mi][nt][2 * h + 1], kp.y, s);
                        }
                        prt[(mi * 2 + h) * 3 + dd] = s;
                    }
                }
#pragma unroll
            for (int i = 0; i < 12; i++) {
                float v = prt[i];
                v += __shfl_xor_sync(0xffffffffu, v, 1);
                v += __shfl_xor_sync(0xffffffffu, v, 2);
                prt[i] = v;
            }
            if (qc == 0) {
                float* PT = (float*)(sm + OFF_PT);
#pragma unroll
                for (int mi = 0; mi < 2; mi++)
#pragma unroll
                    for (int h = 0; h < 2; h++) {
                        int r = 32 * rg + 16 * mi + 8 * h + qrow;
#pragma unroll
                        for (int dd = 0; dd < 3; dd++)
                            PT[(dd * 128 + r) * 2 + cg] = prt[(mi * 2 + h) * 3 + dd];
                    }
            }
        }
        __syncthreads();     // PT ready; XH free (GEMM reads done)

        // ---- store X(tn) half A; prefetch half B; softmax ----
        float4 xb[8];
        if (hn) {
            sts_half(0, xa);
            ldg_half(tn, 1, xb);
        }
        if (tid < 128) {
            const float* PT = (const float*)(sm + OFF_PT);
            float* DT = (float*)(sm + OFF_DT);
            int pos = tid, gp = p0 + pos;
            float d0 = PT[(0 * 128 + pos) * 2] + PT[(0 * 128 + pos) * 2 + 1];
            float d1 = PT[(1 * 128 + pos) * 2] + PT[(1 * 128 + pos) * 2 + 1];
            float d2 = PT[(2 * 128 + pos) * 2] + PT[(2 * 128 + pos) * 2 + 1];
            float m = d1;
            if (gp > 0)     m = fmaxf(m, d0);
            if (gp < T - 1) m = fmaxf(m, d2);
            float w0 = (gp > 0)     ? __expf(d0 - m) : 0.f;
            float w1 = __expf(d1 - m);
            float w2 = (gp < T - 1) ? __expf(d2 - m) : 0.f;
            float inv = 1.f / (w0 + w1 + w2);
            DT[pos * 4 + 0] = w0 * inv;
            DT[pos * 4 + 1] = w1 * inv;
            DT[pos * 4 + 2] = w2 * inv;
        }
        __syncthreads();     // DT ready

        // ---- weighted kv sum -> global out (AXIS_H accumulates) ----
        {
            const float* DT = (const float*)(sm + OFF_DT);
            const float4* kf4 = (const float4*)(sm + OFF_KF);
            int pos = tid >> 1, hf = tid & 1;
            float a0 = DT[pos * 4 + 0];
            float a1 = DT[pos * 4 + 1];
            float a2 = DT[pos * 4 + 2];
            const float4* k0 = kf4 + (pos + 0) * (KF_PITCH / 4);
            const float4* k1 = kf4 + (pos + 1) * (KF_PITCH / 4);
            const float4* k2 = kf4 + (pos + 2) * (KF_PITCH / 4);
            float4* go = (float4*)(out + base + (p0 + pos) * sp);
#pragma unroll
            for (int u = 0; u < 16; u++) {
                int c4 = hf * 16 + u;
                float4 v0 = k0[c4], v1 = k1[c4], v2 = k2[c4];
                float4 r;
                r.x = a0 * v0.x + a1 * v1.x + a2 * v2.x;
                r.y = a0 * v0.y + a1 * v1.y + a2 * v2.y;
                r.z = a0 * v0.z + a1 * v1.z + a2 * v2.z;
                r.w = a0 * v0.w + a1 * v1.w + a2 * v2.w;
                if (AXIS_H) {
                    float4 o = go[c4];
                    r.x += o.x; r.y += o.y; r.z += o.z; r.w += o.w;
                }
                go[c4] = r;
            }
        }

        if (hn) sts_half(1, xb);    // X(tn) half B (LDG latency hidden above)
        __syncthreads();            // KF reads done; XH(tn) complete

        if (hn) stage_kv(tn);       // async; waited after GEMM(tn)
    }
}

// ---------------------------------------------------------------------------
extern "C" void kernel_launch(void* const* d_in, const int* in_sizes, int n_in,
                              void* d_out, int out_size) {
    const float* x    = (const float*)d_in[0];
    const float* kv   = (const float*)d_in[1];
    const float* Wq_h = (const float*)d_in[2];
    const float* Wk_h = (const float*)d_in[3];
    const float* Wq_w = (const float*)d_in[4];
    const float* Wk_w = (const float*)d_in[5];
    float* out = (float*)d_out;

    cudaFuncSetAttribute(axial_mma<0>,
                         cudaFuncAttributeMaxDynamicSharedMemorySize, SMEM_TOTAL);
    cudaFuncSetAttribute(axial_mma<1>,
                         cudaFuncAttributeMaxDynamicSharedMemorySize, SMEM_TOTAL);

    int nsm = 148;
    cudaDeviceGetAttribute(&nsm, cudaDevAttrMultiProcessorCount, 0);
    if (nsm <= 0) nsm = 148;
    if (nsm > NTILES) nsm = NTILES;

    compute_M_kernel<<<dim3(128, 2), 128>>>(Wq_h, Wk_h, Wq_w, Wk_w);
    axial_mma<0><<<nsm, 256, SMEM_TOTAL>>>(x, kv, out);   // width: writes
    axial_mma<1><<<nsm, 256, SMEM_TOTAL>>>(x, kv, out);   // height: accumulates
}